// round 1
// baseline (speedup 1.0000x reference)
#include <cuda_runtime.h>

#define BB 8
#define NN 1024
#define HIDD 1024
#define HH 16
#define DD 64
#define M_TOT (BB * NN)   // 8192

// Scratch (static __device__ arrays — allocation-free per harness rules)
__device__ float g_q[BB * HH * NN * DD];    // [B,H,N,D], pre-scaled by 1/sqrt(D)
__device__ float g_k[BB * HH * NN * DD];
__device__ float g_v[BB * HH * NN * DD];
__device__ float g_ctx[BB * NN * HIDD];     // [B,N,H*D]

// ---------------------------------------------------------------------------
// Fused QKV projection: Y = X @ W + b, scattered to [B,H,N,D]; q scaled.
// 128x128 tile, BK=8, 256 threads, 8x8 per-thread register tile.
// grid = (HID/128=8, M/128=64, 3)
// ---------------------------------------------------------------------------
__global__ __launch_bounds__(256) void qkv_gemm_kernel(
    const float* __restrict__ xq, const float* __restrict__ xk, const float* __restrict__ xv,
    const float* __restrict__ Wq, const float* __restrict__ bq,
    const float* __restrict__ Wk, const float* __restrict__ bk,
    const float* __restrict__ Wv, const float* __restrict__ bv)
{
    __shared__ float As[8][128];
    __shared__ float Bs[8][128];

    const int z = blockIdx.z;
    const float* A    = (z == 0) ? xq : (z == 1) ? xk : xv;
    const float* W    = (z == 0) ? Wq : (z == 1) ? Wk : Wv;
    const float* bias = (z == 0) ? bq : (z == 1) ? bk : bv;
    float* Cout       = (z == 0) ? g_q : (z == 1) ? g_k : g_v;
    const float scale = (z == 0) ? 0.125f : 1.0f;   // SCALE = 64^-0.5

    const int tid = threadIdx.x;
    const int tx = tid & 15, ty = tid >> 4;
    const int row0 = blockIdx.y * 128;
    const int col0 = blockIdx.x * 128;

    float acc[8][8];
#pragma unroll
    for (int i = 0; i < 8; i++)
#pragma unroll
        for (int j = 0; j < 8; j++) acc[i][j] = 0.0f;

    const int arow = tid >> 1;          // 0..127
    const int ac4  = (tid & 1) * 4;     // 0 or 4
    const int brow = tid >> 5;          // 0..7
    const int bcol = (tid & 31) * 4;    // 0..124

    const float* Aptr = A + (size_t)(row0 + arow) * HIDD + ac4;
    const float* Wptr = W + (size_t)brow * HIDD + col0 + bcol;

    for (int k0 = 0; k0 < HIDD; k0 += 8) {
        float4 av = *(const float4*)(Aptr + k0);
        float4 wv = *(const float4*)(Wptr + (size_t)k0 * HIDD);
        __syncthreads();
        As[ac4 + 0][arow] = av.x;
        As[ac4 + 1][arow] = av.y;
        As[ac4 + 2][arow] = av.z;
        As[ac4 + 3][arow] = av.w;
        *(float4*)&Bs[brow][bcol] = wv;
        __syncthreads();
#pragma unroll
        for (int kk = 0; kk < 8; kk++) {
            float ra[8], rb[8];
#pragma unroll
            for (int i = 0; i < 8; i++) ra[i] = As[kk][ty * 8 + i];
#pragma unroll
            for (int j = 0; j < 8; j++) rb[j] = Bs[kk][tx * 8 + j];
#pragma unroll
            for (int i = 0; i < 8; i++)
#pragma unroll
                for (int j = 0; j < 8; j++) acc[i][j] += ra[i] * rb[j];
        }
    }

    // Epilogue: add bias, scale, scatter to [B,H,N,D]
#pragma unroll
    for (int i = 0; i < 8; i++) {
        const int row = row0 + ty * 8 + i;     // b*N + n
        const int b = row >> 10, n = row & 1023;
#pragma unroll
        for (int j4 = 0; j4 < 8; j4 += 4) {
            const int col = col0 + tx * 8 + j4;  // h*64 + d, 4-aligned
            const int h = col >> 6, d = col & 63;
            float4 o;
            o.x = (acc[i][j4 + 0] + bias[col + 0]) * scale;
            o.y = (acc[i][j4 + 1] + bias[col + 1]) * scale;
            o.z = (acc[i][j4 + 2] + bias[col + 2]) * scale;
            o.w = (acc[i][j4 + 3] + bias[col + 3]) * scale;
            *(float4*)(Cout + (((size_t)(b * HH + h) * NN + n) * DD + d)) = o;
        }
    }
}

// ---------------------------------------------------------------------------
// Flash attention: per CTA one (b, h, 64-query tile). 256 threads.
// Streams 64-key tiles: S = q·kT + bias, online softmax, O += P·V.
// smem: q[64*64] + kT/P[64*64] + v[64*64] = 48 KB static.
// grid = (N/64=16, H=16, B=8)
// ---------------------------------------------------------------------------
__global__ __launch_bounds__(256) void attn_kernel(const float* __restrict__ bias)
{
    __shared__ float q_s[64 * 64];
    __shared__ float kp_s[64 * 64];   // kT for S-phase, then P for PV-phase
    __shared__ float v_s[64 * 64];

    const int tid = threadIdx.x;
    const int tx = tid & 15, ty = tid >> 4;
    const int q0 = blockIdx.x * 64;
    const int h  = blockIdx.y;
    const int b  = blockIdx.z;

    const float* qg = g_q + ((size_t)(b * HH + h) * NN + q0) * DD;
    const float* kg = g_k + ((size_t)(b * HH + h) * NN) * DD;
    const float* vg = g_v + ((size_t)(b * HH + h) * NN) * DD;
    const float* bg = bias + (((size_t)(b * HH + h) * NN) + q0) * NN;

    // load q tile [64 rows x 64 d], row-major
#pragma unroll
    for (int l = 0; l < 4; l++) {
        const int f = tid + l * 256;
        const int r = f >> 4, d4 = (f & 15) * 4;
        *(float4*)&q_s[r * 64 + d4] = *(const float4*)(qg + r * DD + d4);
    }

    float m_i[4], l_i[4];
    float4 O[4];
#pragma unroll
    for (int i = 0; i < 4; i++) {
        m_i[i] = -1e30f;
        l_i[i] = 0.0f;
        O[i] = make_float4(0.f, 0.f, 0.f, 0.f);
    }

    for (int kt = 0; kt < 16; kt++) {
        const float* kg_t = kg + (size_t)kt * 64 * DD;
        const float* vg_t = vg + (size_t)kt * 64 * DD;

        __syncthreads();   // also covers q_s readiness on first iter
        // load kT (transposed: kp_s[d*64 + key]) and v (row-major)
#pragma unroll
        for (int l = 0; l < 4; l++) {
            const int f = tid + l * 256;
            const int r = f >> 4, d4 = (f & 15) * 4;
            float4 kv = *(const float4*)(kg_t + r * DD + d4);
            kp_s[(d4 + 0) * 64 + r] = kv.x;
            kp_s[(d4 + 1) * 64 + r] = kv.y;
            kp_s[(d4 + 2) * 64 + r] = kv.z;
            kp_s[(d4 + 3) * 64 + r] = kv.w;
            *(float4*)&v_s[r * 64 + d4] = *(const float4*)(vg_t + r * DD + d4);
        }
        __syncthreads();

        // S[4x4] = q (pre-scaled) · kT
        float S[4][4];
#pragma unroll
        for (int i = 0; i < 4; i++)
#pragma unroll
            for (int j = 0; j < 4; j++) S[i][j] = 0.0f;

        for (int d = 0; d < 64; d++) {
            float ra[4], rb[4];
#pragma unroll
            for (int i = 0; i < 4; i++) ra[i] = q_s[(ty * 4 + i) * 64 + d];
#pragma unroll
            for (int j = 0; j < 4; j++) rb[j] = kp_s[d * 64 + tx * 4 + j];
#pragma unroll
            for (int i = 0; i < 4; i++)
#pragma unroll
                for (int j = 0; j < 4; j++) S[i][j] += ra[i] * rb[j];
        }

        // add bias (coalesced float4)
#pragma unroll
        for (int i = 0; i < 4; i++) {
            float4 bv = *(const float4*)(bg + (size_t)(ty * 4 + i) * NN + kt * 64 + tx * 4);
            S[i][0] += bv.x; S[i][1] += bv.y; S[i][2] += bv.z; S[i][3] += bv.w;
        }

        // online softmax (row groups = 16 lanes sharing ty)
#pragma unroll
        for (int i = 0; i < 4; i++) {
            float mx = fmaxf(fmaxf(S[i][0], S[i][1]), fmaxf(S[i][2], S[i][3]));
#pragma unroll
            for (int off = 8; off > 0; off >>= 1)
                mx = fmaxf(mx, __shfl_xor_sync(0xffffffffu, mx, off));
            const float mnew = fmaxf(m_i[i], mx);
            const float corr = __expf(m_i[i] - mnew);
            float rs = 0.0f;
#pragma unroll
            for (int j = 0; j < 4; j++) {
                S[i][j] = __expf(S[i][j] - mnew);
                rs += S[i][j];
            }
#pragma unroll
            for (int off = 8; off > 0; off >>= 1)
                rs += __shfl_xor_sync(0xffffffffu, rs, off);
            l_i[i] = l_i[i] * corr + rs;
            m_i[i] = mnew;
            O[i].x *= corr; O[i].y *= corr; O[i].z *= corr; O[i].w *= corr;
        }

        __syncthreads();   // everyone finished reading kT
        // write P into kp_s as [q][k]
#pragma unroll
        for (int i = 0; i < 4; i++)
            *(float4*)&kp_s[(ty * 4 + i) * 64 + tx * 4] =
                make_float4(S[i][0], S[i][1], S[i][2], S[i][3]);
        __syncthreads();

        // O += P @ V
        for (int kk = 0; kk < 64; kk++) {
            float4 vv = *(const float4*)&v_s[kk * 64 + tx * 4];
#pragma unroll
            for (int i = 0; i < 4; i++) {
                const float p = kp_s[(ty * 4 + i) * 64 + kk];
                O[i].x += p * vv.x;
                O[i].y += p * vv.y;
                O[i].z += p * vv.z;
                O[i].w += p * vv.w;
            }
        }
    }

    // finalize and store ctx[b][n][h*64+d]
#pragma unroll
    for (int i = 0; i < 4; i++) {
        const float inv = 1.0f / l_i[i];
        float4 o = O[i];
        o.x *= inv; o.y *= inv; o.z *= inv; o.w *= inv;
        const int n = q0 + ty * 4 + i;
        *(float4*)(g_ctx + ((size_t)b * NN + n) * HIDD + h * 64 + tx * 4) = o;
    }
}

// ---------------------------------------------------------------------------
// Output projection: out = ctx @ Wo + bo (plain row-major)
// grid = (8, 64, 1)
// ---------------------------------------------------------------------------
__global__ __launch_bounds__(256) void out_gemm_kernel(
    const float* __restrict__ Wo, const float* __restrict__ bo, float* __restrict__ out)
{
    __shared__ float As[8][128];
    __shared__ float Bs[8][128];

    const int tid = threadIdx.x;
    const int tx = tid & 15, ty = tid >> 4;
    const int row0 = blockIdx.y * 128;
    const int col0 = blockIdx.x * 128;

    float acc[8][8];
#pragma unroll
    for (int i = 0; i < 8; i++)
#pragma unroll
        for (int j = 0; j < 8; j++) acc[i][j] = 0.0f;

    const int arow = tid >> 1;
    const int ac4  = (tid & 1) * 4;
    const int brow = tid >> 5;
    const int bcol = (tid & 31) * 4;

    const float* Aptr = g_ctx + (size_t)(row0 + arow) * HIDD + ac4;
    const float* Wptr = Wo + (size_t)brow * HIDD + col0 + bcol;

    for (int k0 = 0; k0 < HIDD; k0 += 8) {
        float4 av = *(const float4*)(Aptr + k0);
        float4 wv = *(const float4*)(Wptr + (size_t)k0 * HIDD);
        __syncthreads();
        As[ac4 + 0][arow] = av.x;
        As[ac4 + 1][arow] = av.y;
        As[ac4 + 2][arow] = av.z;
        As[ac4 + 3][arow] = av.w;
        *(float4*)&Bs[brow][bcol] = wv;
        __syncthreads();
#pragma unroll
        for (int kk = 0; kk < 8; kk++) {
            float ra[8], rb[8];
#pragma unroll
            for (int i = 0; i < 8; i++) ra[i] = As[kk][ty * 8 + i];
#pragma unroll
            for (int j = 0; j < 8; j++) rb[j] = Bs[kk][tx * 8 + j];
#pragma unroll
            for (int i = 0; i < 8; i++)
#pragma unroll
                for (int j = 0; j < 8; j++) acc[i][j] += ra[i] * rb[j];
        }
    }

#pragma unroll
    for (int i = 0; i < 8; i++) {
        const int row = row0 + ty * 8 + i;
#pragma unroll
        for (int j4 = 0; j4 < 8; j4 += 4) {
            const int col = col0 + tx * 8 + j4;
            float4 o;
            o.x = acc[i][j4 + 0] + bo[col + 0];
            o.y = acc[i][j4 + 1] + bo[col + 1];
            o.z = acc[i][j4 + 2] + bo[col + 2];
            o.w = acc[i][j4 + 3] + bo[col + 3];
            *(float4*)(out + (size_t)row * HIDD + col) = o;
        }
    }
}

// ---------------------------------------------------------------------------
// Launch: 3 kernels, all graph-capturable, allocation-free.
// Input order: q, k, v, attn_bias, Wq, bq, Wk, bk, Wv, bv, Wo, bo
// ---------------------------------------------------------------------------
extern "C" void kernel_launch(void* const* d_in, const int* in_sizes, int n_in,
                              void* d_out, int out_size)
{
    (void)in_sizes; (void)n_in; (void)out_size;
    const float* xq   = (const float*)d_in[0];
    const float* xk   = (const float*)d_in[1];
    const float* xv   = (const float*)d_in[2];
    const float* abia = (const float*)d_in[3];
    const float* Wq   = (const float*)d_in[4];
    const float* bq   = (const float*)d_in[5];
    const float* Wk   = (const float*)d_in[6];
    const float* bk   = (const float*)d_in[7];
    const float* Wv   = (const float*)d_in[8];
    const float* bv   = (const float*)d_in[9];
    const float* Wo   = (const float*)d_in[10];
    const float* bo   = (const float*)d_in[11];
    float* out = (float*)d_out;

    qkv_gemm_kernel<<<dim3(HIDD / 128, M_TOT / 128, 3), 256>>>(
        xq, xk, xv, Wq, bq, Wk, bk, Wv, bv);
    attn_kernel<<<dim3(NN / 64, HH, BB), 256>>>(abia);
    out_gemm_kernel<<<dim3(HIDD / 128, M_TOT / 128, 1), 256>>>(Wo, bo, out);
}

// round 3
// speedup vs baseline: 1.0507x; 1.0507x over previous
#include <cuda_runtime.h>
#include <cuda_bf16.h>

#define BB 8
#define NN 1024
#define HIDD 1024
#define HH 16
#define DD 64
#define M_TOT (BB * NN)   // 8192

// ---------------------------------------------------------------------------
// Scratch (static __device__ arrays — allocation-free per harness rules)
// ---------------------------------------------------------------------------
__device__ __nv_bfloat16 g_axh[3ll * M_TOT * HIDD];   // x hi  (q,k,v inputs)
__device__ __nv_bfloat16 g_axl[3ll * M_TOT * HIDD];   // x lo
__device__ __nv_bfloat16 g_bwh[4ll * HIDD * HIDD];    // W^T hi (q,k,v,o) [N,K]
__device__ __nv_bfloat16 g_bwl[4ll * HIDD * HIDD];    // W^T lo
__device__ float g_q[(size_t)BB * HH * NN * DD];      // [B,H,N,D] (q pre-scaled)
__device__ float g_k[(size_t)BB * HH * NN * DD];
__device__ float g_v[(size_t)BB * HH * NN * DD];
__device__ __nv_bfloat16 g_cxh[(size_t)M_TOT * HIDD]; // ctx hi [B*N, H*D]
__device__ __nv_bfloat16 g_cxl[(size_t)M_TOT * HIDD]; // ctx lo

// ---------------------------------------------------------------------------
// PTX helpers (all plain sm_80-era PTX — no sm_103a feature gating)
// ---------------------------------------------------------------------------
__device__ __forceinline__ unsigned smem_u32(const void* p) {
    unsigned a;
    asm("{ .reg .u64 t; cvta.to.shared.u64 t, %1; cvt.u32.u64 %0, t; }"
        : "=r"(a) : "l"(p));
    return a;
}
#define CP_ASYNC16(dst, src) \
    asm volatile("cp.async.cg.shared.global [%0], [%1], 16;" \
                 :: "r"(dst), "l"(src) : "memory")
#define CP_COMMIT() asm volatile("cp.async.commit_group;" ::: "memory")
#define CP_WAIT(n)  asm volatile("cp.async.wait_group %0;" :: "n"(n) : "memory")

#define LDMATRIX_X4(r0, r1, r2, r3, addr) \
    asm volatile("ldmatrix.sync.aligned.m8n8.x4.shared.b16 {%0,%1,%2,%3}, [%4];" \
                 : "=r"(r0), "=r"(r1), "=r"(r2), "=r"(r3) : "r"(addr))

#define MMA_BF16(c, a, b0, b1) \
    asm volatile("mma.sync.aligned.m16n8k16.row.col.f32.bf16.bf16.f32 " \
                 "{%0,%1,%2,%3}, {%4,%5,%6,%7}, {%8,%9}, {%0,%1,%2,%3};" \
                 : "+f"((c)[0]), "+f"((c)[1]), "+f"((c)[2]), "+f"((c)[3]) \
                 : "r"((a)[0]), "r"((a)[1]), "r"((a)[2]), "r"((a)[3]), \
                   "r"(b0), "r"(b1))

#define SWZ(x) ((x) ^ (((x) >> 3) & 0x70))

// ---------------------------------------------------------------------------
// conv_x: fp32 [8192,1024] -> bf16 hi/lo, same layout. grid (8192, 3), 256 thr.
// ---------------------------------------------------------------------------
__global__ __launch_bounds__(256) void conv_x_kernel(
    const float* __restrict__ xq, const float* __restrict__ xk,
    const float* __restrict__ xv)
{
    const int z = blockIdx.y;
    const float* X = (z == 0) ? xq : (z == 1) ? xk : xv;
    __nv_bfloat16* Ah = g_axh + (size_t)z * M_TOT * HIDD;
    __nv_bfloat16* Al = g_axl + (size_t)z * M_TOT * HIDD;

    const size_t i = (size_t)blockIdx.x * 256 + threadIdx.x;  // float4 idx
    float4 v = ((const float4*)X)[i];

    __nv_bfloat16 h0 = __float2bfloat16(v.x), h1 = __float2bfloat16(v.y);
    __nv_bfloat16 h2 = __float2bfloat16(v.z), h3 = __float2bfloat16(v.w);
    float l0 = v.x - __bfloat162float(h0), l1 = v.y - __bfloat162float(h1);
    float l2 = v.z - __bfloat162float(h2), l3 = v.w - __bfloat162float(h3);

    __nv_bfloat162* Ah2 = (__nv_bfloat162*)Ah;
    __nv_bfloat162* Al2 = (__nv_bfloat162*)Al;
    Ah2[2 * i + 0] = __nv_bfloat162(h0, h1);
    Ah2[2 * i + 1] = __nv_bfloat162(h2, h3);
    Al2[2 * i + 0] = __nv_bfloat162(__float2bfloat16(l0), __float2bfloat16(l1));
    Al2[2 * i + 1] = __nv_bfloat162(__float2bfloat16(l2), __float2bfloat16(l3));
}

// ---------------------------------------------------------------------------
// conv_w: W [K,N] fp32 -> B^T [N,K] bf16 hi/lo. grid (32,32,4), block (32,8).
// ---------------------------------------------------------------------------
__global__ void conv_w_kernel(
    const float* __restrict__ Wq, const float* __restrict__ Wk,
    const float* __restrict__ Wv, const float* __restrict__ Wo)
{
    __shared__ float t[32][33];
    const int z = blockIdx.z;
    const float* W = (z == 0) ? Wq : (z == 1) ? Wk : (z == 2) ? Wv : Wo;
    __nv_bfloat16* Bh = g_bwh + (size_t)z * HIDD * HIDD;
    __nv_bfloat16* Bl = g_bwl + (size_t)z * HIDD * HIDD;

    const int tx = threadIdx.x, ty = threadIdx.y;
    const int k0 = blockIdx.x * 32, n0 = blockIdx.y * 32;

#pragma unroll
    for (int i = 0; i < 4; i++)
        t[ty + 8 * i][tx] = W[(size_t)(k0 + ty + 8 * i) * HIDD + n0 + tx];
    __syncthreads();
#pragma unroll
    for (int i = 0; i < 4; i++) {
        const int n = n0 + ty + 8 * i;
        const int k = k0 + tx;
        const float v = t[tx][ty + 8 * i];
        __nv_bfloat16 h = __float2bfloat16(v);
        Bh[(size_t)n * HIDD + k] = h;
        Bl[(size_t)n * HIDD + k] = __float2bfloat16(v - __bfloat162float(h));
    }
}

// ---------------------------------------------------------------------------
// mma.sync bf16 split GEMM. CTA tile M=128 x N=128, BK=64 (bf16).
// 48 stages: 3 split-segments x 16 k-blocks. Double-buffered cp.async (64KB).
// 8 warps in 4(M) x 2(N): each warp 32x64 via m16n8k16. fp32 C in registers.
// is_qkv=1: z selects (x, W, bias, dst), scatter to [B,H,N,D]; q scaled.
// is_qkv=0: ctx(hi/lo) x Wo -> out_param row-major.
// ---------------------------------------------------------------------------
#define GEMM_SMEM (2 * 32768)

__global__ __launch_bounds__(256, 2) void gemm_kernel(
    const float* __restrict__ bq, const float* __restrict__ bk,
    const float* __restrict__ bv, float* out_param, int is_qkv)
{
    extern __shared__ char smem[];
    const unsigned sb = smem_u32(smem);
    const unsigned uA0 = sb, uB0 = sb + 16384;
    const unsigned uA1 = sb + 32768, uB1 = sb + 49152;

    const int tid = threadIdx.x;
    const int wid = tid >> 5, lane = tid & 31;
    const int wm = wid >> 1, wn = wid & 1;          // warp 4x2
    const int m0 = blockIdx.y * 128;
    const int n0 = blockIdx.x * 128;
    const int z = blockIdx.z;

    const __nv_bfloat16 *Ah, *Al, *Bh, *Bl;
    const float* bias;
    float scale;
    float* dst;
    if (is_qkv) {
        Ah = g_axh + (size_t)z * M_TOT * HIDD;
        Al = g_axl + (size_t)z * M_TOT * HIDD;
        Bh = g_bwh + (size_t)z * HIDD * HIDD;
        Bl = g_bwl + (size_t)z * HIDD * HIDD;
        bias = (z == 0) ? bq : (z == 1) ? bk : bv;
        scale = (z == 0) ? 0.125f : 1.0f;
        dst = (z == 0) ? g_q : (z == 1) ? g_k : g_v;
    } else {
        Ah = g_cxh; Al = g_cxl;
        Bh = g_bwh + 3ll * HIDD * HIDD;
        Bl = g_bwl + 3ll * HIDD * HIDD;
        bias = bq;            // bo passed in slot 0
        scale = 1.0f;
        dst = out_param;
    }

    float c[16][4];
#pragma unroll
    for (int i = 0; i < 16; i++)
#pragma unroll
        for (int j = 0; j < 4; j++) c[i][j] = 0.0f;

    // stage loader: seg = s/16 -> (Ah,Bh),(Ah,Bl),(Al,Bh); k0 = (s%16)*64
    auto load_stage = [&](int s, unsigned ua, unsigned ub) {
        const int seg = s >> 4;
        const int kk0 = (s & 15) * 64;
        const __nv_bfloat16* As = (seg < 2) ? Ah : Al;
        const __nv_bfloat16* Bs = (seg == 1) ? Bl : Bh;
#pragma unroll
        for (int t = 0; t < 4; t++) {          // A: 128 rows x 8 x 16B
            const int cix = tid + t * 256;
            const int row = cix >> 3, c16 = cix & 7;
            const void* src = As + (size_t)(m0 + row) * HIDD + kk0 + c16 * 8;
            CP_ASYNC16(ua + SWZ(row * 128 + c16 * 16), src);
        }
#pragma unroll
        for (int t = 0; t < 4; t++) {          // B: 128 rows x 8 x 16B
            const int cix = tid + t * 256;
            const int row = cix >> 3, c16 = cix & 7;
            const void* src = Bs + (size_t)(n0 + row) * HIDD + kk0 + c16 * 8;
            CP_ASYNC16(ub + SWZ(row * 128 + c16 * 16), src);
        }
        CP_COMMIT();
    };

    load_stage(0, uA0, uB0);

    // ldmatrix lane addressing components (tile-local)
    const int a_r = wm * 32 + (lane & 15);              // + mi*16
    const int a_c16 = (lane >> 4);                      // 0/1 within k16
    const int b_r = wn * 64 + ((lane >> 4) & 1) * 8 + (lane & 7);  // + p*16
    const int b_c16 = (lane >> 3) & 1;

    for (int s = 0; s < 48; s++) {
        const unsigned ua = (s & 1) ? uA1 : uA0;
        const unsigned ub = (s & 1) ? uB1 : uB0;
        if (s + 1 < 48) {
            load_stage(s + 1, (s & 1) ? uA0 : uA1, (s & 1) ? uB0 : uB1);
            CP_WAIT(1);
        } else {
            CP_WAIT(0);
        }
        __syncthreads();

#pragma unroll
        for (int ks = 0; ks < 4; ks++) {
            unsigned a[2][4];
#pragma unroll
            for (int mi = 0; mi < 2; mi++) {
                const unsigned addr =
                    ua + SWZ((a_r + mi * 16) * 128 + ks * 32 + a_c16 * 16);
                LDMATRIX_X4(a[mi][0], a[mi][1], a[mi][2], a[mi][3], addr);
            }
            unsigned b[4][4];
#pragma unroll
            for (int p = 0; p < 4; p++) {
                const unsigned addr =
                    ub + SWZ((b_r + p * 16) * 128 + ks * 32 + b_c16 * 16);
                LDMATRIX_X4(b[p][0], b[p][1], b[p][2], b[p][3], addr);
            }
#pragma unroll
            for (int mi = 0; mi < 2; mi++)
#pragma unroll
                for (int p = 0; p < 4; p++) {
                    MMA_BF16(c[mi * 8 + p * 2 + 0], a[mi], b[p][0], b[p][1]);
                    MMA_BF16(c[mi * 8 + p * 2 + 1], a[mi], b[p][2], b[p][3]);
                }
        }
        __syncthreads();
    }

    // Epilogue: bias + scale, scatter.
    const int row_in_frag = lane >> 2;
    const int col_in_frag = (lane & 3) * 2;
#pragma unroll
    for (int mi = 0; mi < 2; mi++) {
#pragma unroll
        for (int nj = 0; nj < 8; nj++) {
            const float* cc = c[mi * 8 + nj];
            const int col = n0 + wn * 64 + nj * 8 + col_in_frag;
            const float b0 = __ldg(bias + col), b1 = __ldg(bias + col + 1);
#pragma unroll
            for (int rr = 0; rr < 2; rr++) {
                const int m = m0 + wm * 32 + mi * 16 + row_in_frag + rr * 8;
                float2 o;
                o.x = (cc[rr * 2 + 0] + b0) * scale;
                o.y = (cc[rr * 2 + 1] + b1) * scale;
                if (is_qkv) {
                    const int bb = m >> 10, n = m & 1023;
                    const int h = col >> 6, d = col & 63;
                    *(float2*)(dst + (((size_t)(bb * HH + h) * NN + n) * DD + d)) = o;
                } else {
                    *(float2*)(dst + (size_t)m * HIDD + col) = o;
                }
            }
        }
    }
}

// ---------------------------------------------------------------------------
// Flash attention (fp32) — epilogue writes ctx hi/lo bf16.
// grid = (16, 16, 8), 256 threads, 48KB static smem.
// ---------------------------------------------------------------------------
__global__ __launch_bounds__(256) void attn_kernel(const float* __restrict__ bias)
{
    __shared__ float q_s[64 * 64];
    __shared__ float kp_s[64 * 64];
    __shared__ float v_s[64 * 64];

    const int tid = threadIdx.x;
    const int tx = tid & 15, ty = tid >> 4;
    const int q0 = blockIdx.x * 64;
    const int h  = blockIdx.y;
    const int b  = blockIdx.z;

    const float* qg = g_q + ((size_t)(b * HH + h) * NN + q0) * DD;
    const float* kg = g_k + ((size_t)(b * HH + h) * NN) * DD;
    const float* vg = g_v + ((size_t)(b * HH + h) * NN) * DD;
    const float* bg = bias + (((size_t)(b * HH + h) * NN) + q0) * NN;

#pragma unroll
    for (int l = 0; l < 4; l++) {
        const int f = tid + l * 256;
        const int r = f >> 4, d4 = (f & 15) * 4;
        *(float4*)&q_s[r * 64 + d4] = *(const float4*)(qg + r * DD + d4);
    }

    float m_i[4], l_i[4];
    float4 O[4];
#pragma unroll
    for (int i = 0; i < 4; i++) {
        m_i[i] = -1e30f; l_i[i] = 0.0f;
        O[i] = make_float4(0.f, 0.f, 0.f, 0.f);
    }

    for (int kt = 0; kt < 16; kt++) {
        const float* kg_t = kg + (size_t)kt * 64 * DD;
        const float* vg_t = vg + (size_t)kt * 64 * DD;

        __syncthreads();
#pragma unroll
        for (int l = 0; l < 4; l++) {
            const int f = tid + l * 256;
            const int r = f >> 4, d4 = (f & 15) * 4;
            float4 kv = *(const float4*)(kg_t + r * DD + d4);
            kp_s[(d4 + 0) * 64 + r] = kv.x;
            kp_s[(d4 + 1) * 64 + r] = kv.y;
            kp_s[(d4 + 2) * 64 + r] = kv.z;
            kp_s[(d4 + 3) * 64 + r] = kv.w;
            *(float4*)&v_s[r * 64 + d4] = *(const float4*)(vg_t + r * DD + d4);
        }
        __syncthreads();

        float S[4][4];
#pragma unroll
        for (int i = 0; i < 4; i++)
#pragma unroll
            for (int j = 0; j < 4; j++) S[i][j] = 0.0f;

        for (int d = 0; d < 64; d++) {
            float ra[4], rb[4];
#pragma unroll
            for (int i = 0; i < 4; i++) ra[i] = q_s[(ty * 4 + i) * 64 + d];
#pragma unroll
            for (int j = 0; j < 4; j++) rb[j] = kp_s[d * 64 + tx * 4 + j];
#pragma unroll
            for (int i = 0; i < 4; i++)
#pragma unroll
                for (int j = 0; j < 4; j++) S[i][j] += ra[i] * rb[j];
        }

#pragma unroll
        for (int i = 0; i < 4; i++) {
            float4 bv = *(const float4*)(bg + (size_t)(ty * 4 + i) * NN + kt * 64 + tx * 4);
            S[i][0] += bv.x; S[i][1] += bv.y; S[i][2] += bv.z; S[i][3] += bv.w;
        }

#pragma unroll
        for (int i = 0; i < 4; i++) {
            float mx = fmaxf(fmaxf(S[i][0], S[i][1]), fmaxf(S[i][2], S[i][3]));
#pragma unroll
            for (int off = 8; off > 0; off >>= 1)
                mx = fmaxf(mx, __shfl_xor_sync(0xffffffffu, mx, off));
            const float mnew = fmaxf(m_i[i], mx);
            const float corr = __expf(m_i[i] - mnew);
            float rs = 0.0f;
#pragma unroll
            for (int j = 0; j < 4; j++) {
                S[i][j] = __expf(S[i][j] - mnew);
                rs += S[i][j];
            }
#pragma unroll
            for (int off = 8; off > 0; off >>= 1)
                rs += __shfl_xor_sync(0xffffffffu, rs, off);
            l_i[i] = l_i[i] * corr + rs;
            m_i[i] = mnew;
            O[i].x *= corr; O[i].y *= corr; O[i].z *= corr; O[i].w *= corr;
        }

        __syncthreads();
#pragma unroll
        for (int i = 0; i < 4; i++)
            *(float4*)&kp_s[(ty * 4 + i) * 64 + tx * 4] =
                make_float4(S[i][0], S[i][1], S[i][2], S[i][3]);
        __syncthreads();

        for (int kk = 0; kk < 64; kk++) {
            float4 vv = *(const float4*)&v_s[kk * 64 + tx * 4];
#pragma unroll
            for (int i = 0; i < 4; i++) {
                const float p = kp_s[(ty * 4 + i) * 64 + kk];
                O[i].x += p * vv.x; O[i].y += p * vv.y;
                O[i].z += p * vv.z; O[i].w += p * vv.w;
            }
        }
    }

    // finalize -> ctx hi/lo bf16
#pragma unroll
    for (int i = 0; i < 4; i++) {
        const float inv = 1.0f / l_i[i];
        float4 o = O[i];
        o.x *= inv; o.y *= inv; o.z *= inv; o.w *= inv;
        const int n = q0 + ty * 4 + i;
        const size_t idx = ((size_t)b * NN + n) * HIDD + h * 64 + tx * 4;

        __nv_bfloat16 h0 = __float2bfloat16(o.x), h1 = __float2bfloat16(o.y);
        __nv_bfloat16 h2 = __float2bfloat16(o.z), h3 = __float2bfloat16(o.w);
        ((__nv_bfloat162*)(g_cxh + idx))[0] = __nv_bfloat162(h0, h1);
        ((__nv_bfloat162*)(g_cxh + idx))[1] = __nv_bfloat162(h2, h3);
        ((__nv_bfloat162*)(g_cxl + idx))[0] = __nv_bfloat162(
            __float2bfloat16(o.x - __bfloat162float(h0)),
            __float2bfloat16(o.y - __bfloat162float(h1)));
        ((__nv_bfloat162*)(g_cxl + idx))[1] = __nv_bfloat162(
            __float2bfloat16(o.z - __bfloat162float(h2)),
            __float2bfloat16(o.w - __bfloat162float(h3)));
    }
}

// ---------------------------------------------------------------------------
// Launch
// ---------------------------------------------------------------------------
extern "C" void kernel_launch(void* const* d_in, const int* in_sizes, int n_in,
                              void* d_out, int out_size)
{
    (void)in_sizes; (void)n_in; (void)out_size;
    const float* xq   = (const float*)d_in[0];
    const float* xk   = (const float*)d_in[1];
    const float* xv   = (const float*)d_in[2];
    const float* abia = (const float*)d_in[3];
    const float* Wq   = (const float*)d_in[4];
    const float* bq   = (const float*)d_in[5];
    const float* Wk   = (const float*)d_in[6];
    const float* bk   = (const float*)d_in[7];
    const float* Wv   = (const float*)d_in[8];
    const float* bv   = (const float*)d_in[9];
    const float* Wo   = (const float*)d_in[10];
    const float* bo   = (const float*)d_in[11];
    float* out = (float*)d_out;

    static int attr_set = 0;
    if (!attr_set) {
        cudaFuncSetAttribute(gemm_kernel,
                             cudaFuncAttributeMaxDynamicSharedMemorySize, GEMM_SMEM);
        attr_set = 1;
    }

    conv_x_kernel<<<dim3(M_TOT * HIDD / 4 / 256, 3), 256>>>(xq, xk, xv);
    conv_w_kernel<<<dim3(32, 32, 4), dim3(32, 8)>>>(Wq, Wk, Wv, Wo);
    // fused QKV projections (mma.sync bf16 split)
    gemm_kernel<<<dim3(8, 64, 3), 256, GEMM_SMEM>>>(bq, bk, bv, nullptr, 1);
    attn_kernel<<<dim3(NN / 64, HH, BB), 256>>>(abia);
    // output projection
    gemm_kernel<<<dim3(8, 64, 1), 256, GEMM_SMEM>>>(bo, nullptr, nullptr, out, 0);
}

// round 4
// speedup vs baseline: 3.0764x; 2.9279x over previous
#include <cuda_runtime.h>
#include <cuda_bf16.h>

#define BB 8
#define NN 1024
#define HIDD 1024
#define HH 16
#define DD 64
#define M_TOT (BB * NN)   // 8192

// ---------------------------------------------------------------------------
// Scratch (static __device__ arrays — allocation-free per harness rules)
// ---------------------------------------------------------------------------
__device__ __nv_bfloat16 g_axh[3ll * M_TOT * HIDD];   // x hi  (q,k,v inputs)
__device__ __nv_bfloat16 g_axl[3ll * M_TOT * HIDD];   // x lo
__device__ __nv_bfloat16 g_bwh[4ll * HIDD * HIDD];    // W^T hi (q,k,v,o) [N,K]
__device__ __nv_bfloat16 g_bwl[4ll * HIDD * HIDD];    // W^T lo
__device__ __nv_bfloat16 g_qh[(size_t)BB * HH * NN * DD];  // [B,H,N,D] pre-scaled
__device__ __nv_bfloat16 g_ql[(size_t)BB * HH * NN * DD];
__device__ __nv_bfloat16 g_kh[(size_t)BB * HH * NN * DD];
__device__ __nv_bfloat16 g_kl[(size_t)BB * HH * NN * DD];
__device__ __nv_bfloat16 g_vth[(size_t)BB * HH * DD * NN]; // [B,H,D,N] transposed
__device__ __nv_bfloat16 g_vtl[(size_t)BB * HH * DD * NN];
__device__ __nv_bfloat16 g_cxh[(size_t)M_TOT * HIDD]; // ctx hi [B*N, H*D]
__device__ __nv_bfloat16 g_cxl[(size_t)M_TOT * HIDD]; // ctx lo

// ---------------------------------------------------------------------------
// PTX helpers (plain sm_80-era PTX — compiles at compute_103)
// ---------------------------------------------------------------------------
__device__ __forceinline__ unsigned smem_u32(const void* p) {
    unsigned a;
    asm("{ .reg .u64 t; cvta.to.shared.u64 t, %1; cvt.u32.u64 %0, t; }"
        : "=r"(a) : "l"(p));
    return a;
}
#define CP_ASYNC16(dst, src) \
    asm volatile("cp.async.cg.shared.global [%0], [%1], 16;" \
                 :: "r"(dst), "l"(src) : "memory")
#define CP_COMMIT() asm volatile("cp.async.commit_group;" ::: "memory")
#define CP_WAIT(n)  asm volatile("cp.async.wait_group %0;" :: "n"(n) : "memory")

#define LDMATRIX_X4(r0, r1, r2, r3, addr) \
    asm volatile("ldmatrix.sync.aligned.m8n8.x4.shared.b16 {%0,%1,%2,%3}, [%4];" \
                 : "=r"(r0), "=r"(r1), "=r"(r2), "=r"(r3) : "r"(addr))

#define MMA_BF16(c, a, b0, b1) \
    asm volatile("mma.sync.aligned.m16n8k16.row.col.f32.bf16.bf16.f32 " \
                 "{%0,%1,%2,%3}, {%4,%5,%6,%7}, {%8,%9}, {%0,%1,%2,%3};" \
                 : "+f"((c)[0]), "+f"((c)[1]), "+f"((c)[2]), "+f"((c)[3]) \
                 : "r"((a)[0]), "r"((a)[1]), "r"((a)[2]), "r"((a)[3]), \
                   "r"(b0), "r"(b1))

#define SWZ(x) ((x) ^ (((x) >> 3) & 0x70))

__device__ __forceinline__ unsigned pack_bf16(float x, float y) {
    __nv_bfloat162 t = __floats2bfloat162_rn(x, y);
    return *(unsigned*)&t;
}
__device__ __forceinline__ void split2(float x, float y, unsigned& h, unsigned& l) {
    __nv_bfloat16 hx = __float2bfloat16(x), hy = __float2bfloat16(y);
    h = pack_bf16(x, y);  // rn == truncation-ish hi; use hx/hy for lo residual
    // ensure hi/lo consistent: recompute h from hx,hy
    __nv_bfloat162 hh; hh.x = hx; hh.y = hy;
    h = *(unsigned*)&hh;
    l = pack_bf16(x - __bfloat162float(hx), y - __bfloat162float(hy));
}

// ---------------------------------------------------------------------------
// conv_x: fp32 [8192,1024] -> bf16 hi/lo. grid (8192, 3), 256 thr.
// ---------------------------------------------------------------------------
__global__ __launch_bounds__(256) void conv_x_kernel(
    const float* __restrict__ xq, const float* __restrict__ xk,
    const float* __restrict__ xv)
{
    const int z = blockIdx.y;
    const float* X = (z == 0) ? xq : (z == 1) ? xk : xv;
    __nv_bfloat16* Ah = g_axh + (size_t)z * M_TOT * HIDD;
    __nv_bfloat16* Al = g_axl + (size_t)z * M_TOT * HIDD;

    const size_t i = (size_t)blockIdx.x * 256 + threadIdx.x;  // float4 idx
    float4 v = ((const float4*)X)[i];

    __nv_bfloat16 h0 = __float2bfloat16(v.x), h1 = __float2bfloat16(v.y);
    __nv_bfloat16 h2 = __float2bfloat16(v.z), h3 = __float2bfloat16(v.w);
    float l0 = v.x - __bfloat162float(h0), l1 = v.y - __bfloat162float(h1);
    float l2 = v.z - __bfloat162float(h2), l3 = v.w - __bfloat162float(h3);

    __nv_bfloat162* Ah2 = (__nv_bfloat162*)Ah;
    __nv_bfloat162* Al2 = (__nv_bfloat162*)Al;
    Ah2[2 * i + 0] = __nv_bfloat162(h0, h1);
    Ah2[2 * i + 1] = __nv_bfloat162(h2, h3);
    Al2[2 * i + 0] = __nv_bfloat162(__float2bfloat16(l0), __float2bfloat16(l1));
    Al2[2 * i + 1] = __nv_bfloat162(__float2bfloat16(l2), __float2bfloat16(l3));
}

// ---------------------------------------------------------------------------
// conv_w: W [K,N] fp32 -> W^T [N,K] bf16 hi/lo. grid (32,32,4), block (32,8).
// ---------------------------------------------------------------------------
__global__ void conv_w_kernel(
    const float* __restrict__ Wq, const float* __restrict__ Wk,
    const float* __restrict__ Wv, const float* __restrict__ Wo)
{
    __shared__ float t[32][33];
    const int z = blockIdx.z;
    const float* W = (z == 0) ? Wq : (z == 1) ? Wk : (z == 2) ? Wv : Wo;
    __nv_bfloat16* Bh = g_bwh + (size_t)z * HIDD * HIDD;
    __nv_bfloat16* Bl = g_bwl + (size_t)z * HIDD * HIDD;

    const int tx = threadIdx.x, ty = threadIdx.y;
    const int k0 = blockIdx.x * 32, n0 = blockIdx.y * 32;

#pragma unroll
    for (int i = 0; i < 4; i++)
        t[ty + 8 * i][tx] = W[(size_t)(k0 + ty + 8 * i) * HIDD + n0 + tx];
    __syncthreads();
#pragma unroll
    for (int i = 0; i < 4; i++) {
        const int n = n0 + ty + 8 * i;
        const int k = k0 + tx;
        const float v = t[tx][ty + 8 * i];
        __nv_bfloat16 h = __float2bfloat16(v);
        Bh[(size_t)n * HIDD + k] = h;
        Bl[(size_t)n * HIDD + k] = __float2bfloat16(v - __bfloat162float(h));
    }
}

// ---------------------------------------------------------------------------
// mma.sync bf16 split GEMM (unchanged mainloop from R3).
// is_qkv=1: epilogue emits bf16 hi/lo; q scaled; v transposed to [B,H,D,N].
// is_qkv=0: ctx(hi/lo) x Wo -> fp32 out row-major.
// ---------------------------------------------------------------------------
#define GEMM_SMEM (2 * 32768)

__global__ __launch_bounds__(256, 2) void gemm_kernel(
    const float* __restrict__ bq, const float* __restrict__ bk,
    const float* __restrict__ bv, float* out_param, int is_qkv)
{
    extern __shared__ char smem[];
    const unsigned sb = smem_u32(smem);
    const unsigned uA0 = sb, uB0 = sb + 16384;
    const unsigned uA1 = sb + 32768, uB1 = sb + 49152;

    const int tid = threadIdx.x;
    const int wid = tid >> 5, lane = tid & 31;
    const int wm = wid >> 1, wn = wid & 1;          // warp 4x2
    const int m0 = blockIdx.y * 128;
    const int n0 = blockIdx.x * 128;
    const int z = blockIdx.z;

    const __nv_bfloat16 *Ah, *Al, *Bh, *Bl;
    const float* bias;
    float scale;
    if (is_qkv) {
        Ah = g_axh + (size_t)z * M_TOT * HIDD;
        Al = g_axl + (size_t)z * M_TOT * HIDD;
        Bh = g_bwh + (size_t)z * HIDD * HIDD;
        Bl = g_bwl + (size_t)z * HIDD * HIDD;
        bias = (z == 0) ? bq : (z == 1) ? bk : bv;
        scale = (z == 0) ? 0.125f : 1.0f;
    } else {
        Ah = g_cxh; Al = g_cxl;
        Bh = g_bwh + 3ll * HIDD * HIDD;
        Bl = g_bwl + 3ll * HIDD * HIDD;
        bias = bq;            // bo passed in slot 0
        scale = 1.0f;
    }

    float c[16][4];
#pragma unroll
    for (int i = 0; i < 16; i++)
#pragma unroll
        for (int j = 0; j < 4; j++) c[i][j] = 0.0f;

    auto load_stage = [&](int s, unsigned ua, unsigned ub) {
        const int seg = s >> 4;
        const int kk0 = (s & 15) * 64;
        const __nv_bfloat16* As = (seg < 2) ? Ah : Al;
        const __nv_bfloat16* Bs = (seg == 1) ? Bl : Bh;
#pragma unroll
        for (int t = 0; t < 4; t++) {
            const int cix = tid + t * 256;
            const int row = cix >> 3, c16 = cix & 7;
            const void* src = As + (size_t)(m0 + row) * HIDD + kk0 + c16 * 8;
            CP_ASYNC16(ua + SWZ(row * 128 + c16 * 16), src);
        }
#pragma unroll
        for (int t = 0; t < 4; t++) {
            const int cix = tid + t * 256;
            const int row = cix >> 3, c16 = cix & 7;
            const void* src = Bs + (size_t)(n0 + row) * HIDD + kk0 + c16 * 8;
            CP_ASYNC16(ub + SWZ(row * 128 + c16 * 16), src);
        }
        CP_COMMIT();
    };

    load_stage(0, uA0, uB0);

    const int a_r = wm * 32 + (lane & 15);
    const int a_c16 = (lane >> 4);
    const int b_r = wn * 64 + ((lane >> 4) & 1) * 8 + (lane & 7);
    const int b_c16 = (lane >> 3) & 1;

    for (int s = 0; s < 48; s++) {
        const unsigned ua = (s & 1) ? uA1 : uA0;
        const unsigned ub = (s & 1) ? uB1 : uB0;
        if (s + 1 < 48) {
            load_stage(s + 1, (s & 1) ? uA0 : uA1, (s & 1) ? uB0 : uB1);
            CP_WAIT(1);
        } else {
            CP_WAIT(0);
        }
        __syncthreads();

#pragma unroll
        for (int ks = 0; ks < 4; ks++) {
            unsigned a[2][4];
#pragma unroll
            for (int mi = 0; mi < 2; mi++) {
                const unsigned addr =
                    ua + SWZ((a_r + mi * 16) * 128 + ks * 32 + a_c16 * 16);
                LDMATRIX_X4(a[mi][0], a[mi][1], a[mi][2], a[mi][3], addr);
            }
            unsigned b[4][4];
#pragma unroll
            for (int p = 0; p < 4; p++) {
                const unsigned addr =
                    ub + SWZ((b_r + p * 16) * 128 + ks * 32 + b_c16 * 16);
                LDMATRIX_X4(b[p][0], b[p][1], b[p][2], b[p][3], addr);
            }
#pragma unroll
            for (int mi = 0; mi < 2; mi++)
#pragma unroll
                for (int p = 0; p < 4; p++) {
                    MMA_BF16(c[mi * 8 + p * 2 + 0], a[mi], b[p][0], b[p][1]);
                    MMA_BF16(c[mi * 8 + p * 2 + 1], a[mi], b[p][2], b[p][3]);
                }
        }
        __syncthreads();
    }

    // Epilogue
    const int row_in_frag = lane >> 2;
    const int col_in_frag = (lane & 3) * 2;
#pragma unroll
    for (int mi = 0; mi < 2; mi++) {
#pragma unroll
        for (int nj = 0; nj < 8; nj++) {
            const float* cc = c[mi * 8 + nj];
            const int col = n0 + wn * 64 + nj * 8 + col_in_frag;
            const float b0 = __ldg(bias + col), b1 = __ldg(bias + col + 1);
#pragma unroll
            for (int rr = 0; rr < 2; rr++) {
                const int m = m0 + wm * 32 + mi * 16 + row_in_frag + rr * 8;
                float ox = (cc[rr * 2 + 0] + b0) * scale;
                float oy = (cc[rr * 2 + 1] + b1) * scale;
                if (is_qkv) {
                    const int bb = m >> 10, n = m & 1023;
                    const int h = col >> 6, d = col & 63;
                    __nv_bfloat16 hx = __float2bfloat16(ox);
                    __nv_bfloat16 hy = __float2bfloat16(oy);
                    __nv_bfloat16 lx = __float2bfloat16(ox - __bfloat162float(hx));
                    __nv_bfloat16 ly = __float2bfloat16(oy - __bfloat162float(hy));
                    if (z == 2) {   // V: transposed store [B,H,D,N]
                        const size_t base = ((size_t)(bb * HH + h) * DD + d) * NN + n;
                        g_vth[base] = hx;       g_vtl[base] = lx;
                        g_vth[base + NN] = hy;  g_vtl[base + NN] = ly;
                    } else {
                        const size_t idx = (((size_t)(bb * HH + h) * NN + n) * DD + d);
                        __nv_bfloat16* dh = (z == 0) ? g_qh : g_kh;
                        __nv_bfloat16* dl = (z == 0) ? g_ql : g_kl;
                        *(__nv_bfloat162*)(dh + idx) = __nv_bfloat162(hx, hy);
                        *(__nv_bfloat162*)(dl + idx) = __nv_bfloat162(lx, ly);
                    }
                } else {
                    float2 o; o.x = ox; o.y = oy;
                    *(float2*)(out_param + (size_t)m * HIDD + col) = o;
                }
            }
        }
    }
}

// ---------------------------------------------------------------------------
// Tensor-core flash attention (split-bf16, fp32 softmax/accum).
// CTA: 128 queries, 8 warps (16 rows each). 16 key tiles of 64.
// smem: q hi/lo [128][64] + k hi/lo [64][64] + v^T hi/lo [64][64],
// padded row stride 72 elems (144B). grid (8, 16, 8), 256 threads.
// ---------------------------------------------------------------------------
#define OQH 0
#define OQL 18432
#define OKH 36864
#define OKL 46080
#define OVH 55296
#define OVL 64512
#define ATTN_SMEM 73728

__global__ __launch_bounds__(256, 2) void attn_kernel(const float* __restrict__ bias)
{
    extern __shared__ char smem[];
    const unsigned sb = smem_u32(smem);

    const int tid = threadIdx.x;
    const int wid = tid >> 5, lane = tid & 31;
    const int q0 = blockIdx.x * 128;
    const int h  = blockIdx.y;
    const int b  = blockIdx.z;

    const size_t qbase  = ((size_t)(b * HH + h) * NN + q0) * DD;
    const size_t kbase  = ((size_t)(b * HH + h) * NN) * DD;
    const size_t vtbase = ((size_t)(b * HH + h) * DD) * NN;

    // Load Q hi/lo: 1024 chunks of 16B each array
#pragma unroll
    for (int t = 0; t < 4; t++) {
        const int ch = tid + t * 256;
        const int row = ch >> 3, c16 = ch & 7;
        CP_ASYNC16(sb + OQH + row * 144 + c16 * 16, g_qh + qbase + row * 64 + c16 * 8);
        CP_ASYNC16(sb + OQL + row * 144 + c16 * 16, g_ql + qbase + row * 64 + c16 * 8);
    }
    CP_COMMIT();

    float O[8][4];
#pragma unroll
    for (int i = 0; i < 8; i++)
#pragma unroll
        for (int j = 0; j < 4; j++) O[i][j] = 0.0f;
    float m1 = -1e30f, m2 = -1e30f, l1 = 0.0f, l2 = 0.0f;

    // ldmatrix lane addressing
    const unsigned qh_a = sb + OQH + (wid * 16 + (lane & 15)) * 144 + (lane >> 4) * 16;
    const unsigned ql_a = qh_a + (OQL - OQH);
    const int nrow = ((lane >> 4) & 1) * 8 + (lane & 7);
    const int nc16 = (lane >> 3) & 1;
    const unsigned kh_a = sb + OKH + nrow * 144 + nc16 * 16;
    const unsigned kl_a = kh_a + (OKL - OKH);
    const unsigned vh_a = sb + OVH + nrow * 144 + nc16 * 16;
    const unsigned vl_a = vh_a + (OVL - OVH);

    const int r1 = lane >> 2;
    const int cq = (lane & 3) * 2;
    const float* bgq = bias + ((size_t)(b * HH + h) * NN + q0 + wid * 16) * NN;

    for (int kt = 0; kt < 16; kt++) {
        __syncthreads();
#pragma unroll
        for (int t = 0; t < 2; t++) {
            const int ch = tid + t * 256;
            const int row = ch >> 3, c16 = ch & 7;
            CP_ASYNC16(sb + OKH + row * 144 + c16 * 16,
                       g_kh + kbase + (size_t)(kt * 64 + row) * 64 + c16 * 8);
            CP_ASYNC16(sb + OKL + row * 144 + c16 * 16,
                       g_kl + kbase + (size_t)(kt * 64 + row) * 64 + c16 * 8);
            CP_ASYNC16(sb + OVH + row * 144 + c16 * 16,
                       g_vth + vtbase + (size_t)row * NN + kt * 64 + c16 * 8);
            CP_ASYNC16(sb + OVL + row * 144 + c16 * 16,
                       g_vtl + vtbase + (size_t)row * NN + kt * 64 + c16 * 8);
        }
        CP_COMMIT();
        CP_WAIT(0);
        __syncthreads();

        // ---- S = qh*kh^T + qh*kl^T + ql*kh^T  (128x64, per-warp 16x64) ----
        float S[8][4];
#pragma unroll
        for (int i = 0; i < 8; i++)
#pragma unroll
            for (int j = 0; j < 4; j++) S[i][j] = 0.0f;

#pragma unroll
        for (int j = 0; j < 4; j++) {       // k16 over d
            unsigned aqh[4], aql[4];
            LDMATRIX_X4(aqh[0], aqh[1], aqh[2], aqh[3], qh_a + j * 32);
            LDMATRIX_X4(aql[0], aql[1], aql[2], aql[3], ql_a + j * 32);
#pragma unroll
            for (int g = 0; g < 4; g++) {   // n16 over keys
                unsigned bh[4], bl[4];
                LDMATRIX_X4(bh[0], bh[1], bh[2], bh[3], kh_a + g * (16 * 144) + j * 32);
                LDMATRIX_X4(bl[0], bl[1], bl[2], bl[3], kl_a + g * (16 * 144) + j * 32);
                MMA_BF16(S[2 * g + 0], aqh, bh[0], bh[1]);
                MMA_BF16(S[2 * g + 1], aqh, bh[2], bh[3]);
                MMA_BF16(S[2 * g + 0], aqh, bl[0], bl[1]);
                MMA_BF16(S[2 * g + 1], aqh, bl[2], bl[3]);
                MMA_BF16(S[2 * g + 0], aql, bh[0], bh[1]);
                MMA_BF16(S[2 * g + 1], aql, bh[2], bh[3]);
            }
        }

        // ---- bias add ----
        const float* bt = bgq + kt * 64;
#pragma unroll
        for (int j = 0; j < 8; j++) {
            float2 f0 = *(const float2*)(bt + (size_t)r1 * NN + 8 * j + cq);
            float2 f1 = *(const float2*)(bt + (size_t)(r1 + 8) * NN + 8 * j + cq);
            S[j][0] += f0.x; S[j][1] += f0.y;
            S[j][2] += f1.x; S[j][3] += f1.y;
        }

        // ---- online softmax (rows r1, r1+8; quad shfl) ----
        float mx1 = -1e30f, mx2 = -1e30f;
#pragma unroll
        for (int j = 0; j < 8; j++) {
            mx1 = fmaxf(mx1, fmaxf(S[j][0], S[j][1]));
            mx2 = fmaxf(mx2, fmaxf(S[j][2], S[j][3]));
        }
        mx1 = fmaxf(mx1, __shfl_xor_sync(0xffffffffu, mx1, 1));
        mx1 = fmaxf(mx1, __shfl_xor_sync(0xffffffffu, mx1, 2));
        mx2 = fmaxf(mx2, __shfl_xor_sync(0xffffffffu, mx2, 1));
        mx2 = fmaxf(mx2, __shfl_xor_sync(0xffffffffu, mx2, 2));
        const float mn1 = fmaxf(m1, mx1);
        const float mn2 = fmaxf(m2, mx2);
        const float co1 = __expf(m1 - mn1);
        const float co2 = __expf(m2 - mn2);
        float rs1 = 0.0f, rs2 = 0.0f;
#pragma unroll
        for (int j = 0; j < 8; j++) {
            S[j][0] = __expf(S[j][0] - mn1);
            S[j][1] = __expf(S[j][1] - mn1);
            S[j][2] = __expf(S[j][2] - mn2);
            S[j][3] = __expf(S[j][3] - mn2);
            rs1 += S[j][0] + S[j][1];
            rs2 += S[j][2] + S[j][3];
        }
        rs1 += __shfl_xor_sync(0xffffffffu, rs1, 1);
        rs1 += __shfl_xor_sync(0xffffffffu, rs1, 2);
        rs2 += __shfl_xor_sync(0xffffffffu, rs2, 1);
        rs2 += __shfl_xor_sync(0xffffffffu, rs2, 2);
        l1 = l1 * co1 + rs1;  m1 = mn1;
        l2 = l2 * co2 + rs2;  m2 = mn2;
#pragma unroll
        for (int i = 0; i < 8; i++) {
            O[i][0] *= co1; O[i][1] *= co1;
            O[i][2] *= co2; O[i][3] *= co2;
        }

        // ---- O += Ph*Vh + Ph*Vl + Pl*Vh  (per-warp 16x64) ----
#pragma unroll
        for (int j = 0; j < 4; j++) {       // k16 over keys
            unsigned aph[4], apl[4];
            split2(S[2 * j][0],     S[2 * j][1],     aph[0], apl[0]);
            split2(S[2 * j][2],     S[2 * j][3],     aph[1], apl[1]);
            split2(S[2 * j + 1][0], S[2 * j + 1][1], aph[2], apl[2]);
            split2(S[2 * j + 1][2], S[2 * j + 1][3], aph[3], apl[3]);
#pragma unroll
            for (int g = 0; g < 4; g++) {   // n16 over d
                unsigned bh[4], bl[4];
                LDMATRIX_X4(bh[0], bh[1], bh[2], bh[3], vh_a + g * (16 * 144) + j * 32);
                LDMATRIX_X4(bl[0], bl[1], bl[2], bl[3], vl_a + g * (16 * 144) + j * 32);
                MMA_BF16(O[2 * g + 0], aph, bh[0], bh[1]);
                MMA_BF16(O[2 * g + 1], aph, bh[2], bh[3]);
                MMA_BF16(O[2 * g + 0], aph, bl[0], bl[1]);
                MMA_BF16(O[2 * g + 1], aph, bl[2], bl[3]);
                MMA_BF16(O[2 * g + 0], apl, bh[0], bh[1]);
                MMA_BF16(O[2 * g + 1], apl, bh[2], bh[3]);
            }
        }
    }

    // ---- finalize -> ctx hi/lo bf16 ----
    const float inv1 = 1.0f / l1, inv2 = 1.0f / l2;
    const int n1 = q0 + wid * 16 + r1;
    const int n2 = n1 + 8;
#pragma unroll
    for (int i = 0; i < 8; i++) {
        const int d = 8 * i + cq;
        float x = O[i][0] * inv1, y = O[i][1] * inv1;
        float z = O[i][2] * inv2, w = O[i][3] * inv2;

        __nv_bfloat16 hx = __float2bfloat16(x), hy = __float2bfloat16(y);
        __nv_bfloat16 hz = __float2bfloat16(z), hw = __float2bfloat16(w);
        const size_t i1 = ((size_t)b * NN + n1) * HIDD + h * 64 + d;
        const size_t i2 = ((size_t)b * NN + n2) * HIDD + h * 64 + d;
        *(__nv_bfloat162*)(g_cxh + i1) = __nv_bfloat162(hx, hy);
        *(__nv_bfloat162*)(g_cxh + i2) = __nv_bfloat162(hz, hw);
        *(__nv_bfloat162*)(g_cxl + i1) = __nv_bfloat162(
            __float2bfloat16(x - __bfloat162float(hx)),
            __float2bfloat16(y - __bfloat162float(hy)));
        *(__nv_bfloat162*)(g_cxl + i2) = __nv_bfloat162(
            __float2bfloat16(z - __bfloat162float(hz)),
            __float2bfloat16(w - __bfloat162float(hw)));
    }
}

// ---------------------------------------------------------------------------
// Launch
// ---------------------------------------------------------------------------
extern "C" void kernel_launch(void* const* d_in, const int* in_sizes, int n_in,
                              void* d_out, int out_size)
{
    (void)in_sizes; (void)n_in; (void)out_size;
    const float* xq   = (const float*)d_in[0];
    const float* xk   = (const float*)d_in[1];
    const float* xv   = (const float*)d_in[2];
    const float* abia = (const float*)d_in[3];
    const float* bq   = (const float*)d_in[5];
    const float* Wq   = (const float*)d_in[4];
    const float* Wk   = (const float*)d_in[6];
    const float* bk   = (const float*)d_in[7];
    const float* Wv   = (const float*)d_in[8];
    const float* bv   = (const float*)d_in[9];
    const float* Wo   = (const float*)d_in[10];
    const float* bo   = (const float*)d_in[11];
    float* out = (float*)d_out;

    static int attr_set = 0;
    if (!attr_set) {
        cudaFuncSetAttribute(gemm_kernel,
                             cudaFuncAttributeMaxDynamicSharedMemorySize, GEMM_SMEM);
        cudaFuncSetAttribute(attn_kernel,
                             cudaFuncAttributeMaxDynamicSharedMemorySize, ATTN_SMEM);
        attr_set = 1;
    }

    conv_x_kernel<<<dim3(M_TOT * HIDD / 4 / 256, 3), 256>>>(xq, xk, xv);
    conv_w_kernel<<<dim3(32, 32, 4), dim3(32, 8)>>>(Wq, Wk, Wv, Wo);
    gemm_kernel<<<dim3(8, 64, 3), 256, GEMM_SMEM>>>(bq, bk, bv, nullptr, 1);
    attn_kernel<<<dim3(8, 16, 8), 256, ATTN_SMEM>>>(abia);
    gemm_kernel<<<dim3(8, 64, 1), 256, GEMM_SMEM>>>(bo, nullptr, nullptr, out, 0);
}